// round 6
// baseline (speedup 1.0000x reference)
#include <cuda_runtime.h>

#define N_NODES 10000
#define N_EDGES 320000
#define D_IN    128
#define D_HID   64
#define D_OUT   16
#define NH      (N_NODES * D_HID)
#define AAM     5
#define TPB         512
#define GRID_BLOCKS 296              // 148 SMs x 2 blocks guaranteed resident
#define NWARPS      (GRID_BLOCKS * (TPB / 32))   // 4736
#define NTHREADS    (GRID_BLOCKS * TPB)
#define NODE_COST   48
#define COST_TOTAL  (N_EDGES + NODE_COST * N_NODES)

typedef unsigned long long ull;

// ---------------- device scratch ----------------
__device__ float  g_b[NH];
__device__ float  g_u[NH];
__device__ float  g_wbuf[2][NH];          // ping-pong SPMM input
__device__ float  g_F[AAM][NH];
__device__ float  g_G[AAM][NH];
__device__ float  g_ThT[D_HID * D_HID];   // ThT[k*64+c] = Theta[c][k]
__device__ int    g_rowptr[N_NODES + 1];
__device__ int    g_cur[N_NODES];
__device__ int2   g_edge[N_EDGES];
__device__ int    g_wstart[NWARPS + 1];
__device__ double g_GGbuf[2][15];
__device__ double g_GGrow[2][5];
__device__ unsigned          g_bar_cnt;
__device__ volatile unsigned g_bar_gen;

union SmemU {
    struct { float M[64][128]; float fct[64]; } th;
    ull  sThU[D_HID][32];                 // packed Theta pairs for mix
    int  part[TPB];
};

// ---------------- f32x2 helpers ----------------
__device__ __forceinline__ void fma2(ull& d, ull a, ull b) {
    asm("fma.rn.f32x2 %0, %1, %2, %0;" : "+l"(d) : "l"(a), "l"(b));
}
__device__ __forceinline__ ull splat2(float s) {
    ull r; asm("mov.b64 %0, {%1, %1};" : "=l"(r) : "f"(s)); return r;
}
__device__ __forceinline__ float2 unpack2(ull v) {
    float2 r; asm("mov.b64 {%0, %1}, %2;" : "=f"(r.x), "=f"(r.y) : "l"(v)); return r;
}

// ---------------- software grid barrier ----------------
__device__ __forceinline__ void gbar() {
    __syncthreads();
    if (threadIdx.x == 0) {
        __threadfence();
        unsigned gen = g_bar_gen;
        if (atomicAdd(&g_bar_cnt, 1u) == GRID_BLOCKS - 1u) {
            g_bar_cnt = 0u;
            __threadfence();
            g_bar_gen = gen + 1u;
        } else {
            while (g_bar_gen == gen) { __nanosleep(64); }
        }
        __threadfence();
    }
    __syncthreads();
}

// ---------------- Cayley: Theta = (I+Om)^-1 (I-Om) ----------------
__device__ void theta_phase(const float* __restrict__ B, SmemU* su) {
    int tid = threadIdx.x;
    for (int idx = tid; idx < 64 * 64; idx += TPB) {
        int i = idx >> 6, j = idx & 63;
        float om = 0.5f * (B[i * 64 + j] - B[j * 64 + i]);
        float e  = (i == j) ? 1.f : 0.f;
        su->th.M[i][j]      = e + om;
        su->th.M[i][64 + j] = e - om;
    }
    __syncthreads();
    for (int k = 0; k < 64; k++) {
        float inv = 1.f / su->th.M[k][k];
        __syncthreads();
        for (int j = tid; j < 128; j += TPB) su->th.M[k][j] *= inv;
        __syncthreads();
        for (int r = tid; r < 64; r += TPB) su->th.fct[r] = su->th.M[r][k];
        __syncthreads();
        for (int idx = tid; idx < 64 * 128; idx += TPB) {
            int r = idx >> 7, j = idx & 127;
            if (r != k) su->th.M[r][j] -= su->th.fct[r] * su->th.M[k][j];
        }
        __syncthreads();
    }
    for (int idx = tid; idx < 64 * 64; idx += TPB) {
        int k = idx >> 6, c = idx & 63;
        g_ThT[idx] = su->th.M[c][64 + k];
    }
}

// ---------------- encoder + u0/w0 (x staged through smem) ----------------
__device__ void encode_phase(const float* __restrict__ x, const float* __restrict__ W,
                             const float* __restrict__ bias, int2 (*sedge)[64]) {
    int warp = threadIdx.x >> 5, cp = threadIdx.x & 31;
    int g = blockIdx.x * (TPB / 32) + warp;
    const float2* __restrict__ W2 = (const float2*)W;
    float4* sx = (float4*)&sedge[warp][0];     // 512B = 32 float4 = one x row
    float2 bsv = ((const float2*)bias)[cp];
    for (int node = g; node < N_NODES; node += NWARPS) {
        float4 xq = ((const float4*)(x + node * D_IN))[cp];
        sx[cp] = xq;
        __syncwarp();
        const float* xs = (const float*)sx;
        float2 acc = bsv;
#pragma unroll 16
        for (int k = 0; k < D_IN; k++) {
            float  xk = xs[k];
            float2 w2 = W2[k * 32 + cp];
            acc.x = fmaf(xk, w2.x, acc.x);
            acc.y = fmaf(xk, w2.y, acc.y);
        }
        __syncwarp();
        int row = node * 32 + cp;
        ((float2*)g_b)[row] = acc;
        ((float2*)g_u)[row] = acc;
        ((float2*)g_wbuf[0])[row] = make_float2(2.f * fmaxf(acc.x, 0.f),
                                                2.f * fmaxf(acc.y, 0.f));
    }
}

// ---------------- gather from staged smem edges ----------------
__device__ __forceinline__ float2 gather_smem(const int2* __restrict__ se, int cnt,
                                              const float2* __restrict__ wv, int lane) {
    float2 a0 = make_float2(0.f, 0.f), a1 = make_float2(0.f, 0.f);
    float2 a2 = make_float2(0.f, 0.f), a3 = make_float2(0.f, 0.f);
    int i = 0;
    for (; i + 8 <= cnt; i += 8) {
        int2 d0 = se[i],     d1 = se[i + 1], d2 = se[i + 2], d3 = se[i + 3];
        int2 d4 = se[i + 4], d5 = se[i + 5], d6 = se[i + 6], d7 = se[i + 7];
        float2 v0 = wv[d0.x * 32 + lane], v1 = wv[d1.x * 32 + lane];
        float2 v2 = wv[d2.x * 32 + lane], v3 = wv[d3.x * 32 + lane];
        float2 v4 = wv[d4.x * 32 + lane], v5 = wv[d5.x * 32 + lane];
        float2 v6 = wv[d6.x * 32 + lane], v7 = wv[d7.x * 32 + lane];
        float w0 = __int_as_float(d0.y), w1 = __int_as_float(d1.y);
        float w2 = __int_as_float(d2.y), w3 = __int_as_float(d3.y);
        float w4 = __int_as_float(d4.y), w5 = __int_as_float(d5.y);
        float w6 = __int_as_float(d6.y), w7 = __int_as_float(d7.y);
        a0.x = fmaf(w0, v0.x, a0.x); a0.y = fmaf(w0, v0.y, a0.y);
        a1.x = fmaf(w1, v1.x, a1.x); a1.y = fmaf(w1, v1.y, a1.y);
        a2.x = fmaf(w2, v2.x, a2.x); a2.y = fmaf(w2, v2.y, a2.y);
        a3.x = fmaf(w3, v3.x, a3.x); a3.y = fmaf(w3, v3.y, a3.y);
        a0.x = fmaf(w4, v4.x, a0.x); a0.y = fmaf(w4, v4.y, a0.y);
        a1.x = fmaf(w5, v5.x, a1.x); a1.y = fmaf(w5, v5.y, a1.y);
        a2.x = fmaf(w6, v6.x, a2.x); a2.y = fmaf(w6, v6.y, a2.y);
        a3.x = fmaf(w7, v7.x, a3.x); a3.y = fmaf(w7, v7.y, a3.y);
    }
    for (; i < cnt; ++i) {
        int2 d = se[i];
        float2 v = wv[d.x * 32 + lane];
        float ww = __int_as_float(d.y);
        a0.x = fmaf(ww, v.x, a0.x); a0.y = fmaf(ww, v.y, a0.y);
    }
    return make_float2(a0.x + a1.x + a2.x + a3.x, a0.y + a1.y + a2.y + a3.y);
}

// ---------------- fused SPMM + mix + G + Gram partials ----------------
__device__ void spmm_phase(int slot, int npairs, double* target, int wr_next,
                           const float* __restrict__ wsrc, float* __restrict__ wdst,
                           SmemU* su, int2 (*sedge)[64], double (*red)[5]) {
    int warp = threadIdx.x >> 5, lane = threadIdx.x & 31;
    int w = blockIdx.x * (TPB / 32) + warp;
    const int2*   __restrict__ eg = g_edge;
    const float2* __restrict__ wv = (const float2*)wsrc;
    float p[5];
#pragma unroll
    for (int j = 0; j < 5; j++) p[j] = 0.f;

    int ns = g_wstart[w], ne = g_wstart[w + 1];
    if (ns < ne) {
        int beg = g_rowptr[ns], end = g_rowptr[ns + 1];
        // prefetch node ns round-0 edges into registers
        int2 ed0 = make_int2(0, 0), ed1 = make_int2(0, 0);
        if (beg + lane < end)      ed0 = eg[beg + lane];
        if (beg + 32 + lane < end) ed1 = eg[beg + 32 + lane];

        for (int n = ns; n < ne; ++n) {
            sedge[warp][lane]      = ed0;
            sedge[warp][32 + lane] = ed1;
            __syncwarp();
            int row = n * 32 + lane;
            float2 bb = ((const float2*)g_b)[row];   // prefetch epilogue data
            float2 uu = ((const float2*)g_u)[row];
            int cnt = end - beg;
            const int2* se = &sedge[warp][0];
            float2 acc = gather_smem(se, (cnt < 64) ? cnt : 64, wv, lane);
            // slow path: degree > 64 (rare)
            for (int base = beg + 64; base < end; base += 64) {
                __syncwarp();
                int m = end - base;
                if (lane < m)      sedge[warp][lane]      = eg[base + lane];
                if (32 + lane < m) sedge[warp][32 + lane] = eg[base + 32 + lane];
                __syncwarp();
                float2 ax = gather_smem(se, (m < 64) ? m : 64, wv, lane);
                acc.x += ax.x; acc.y += ax.y;
            }
            __syncwarp();   // all LDS done before next iteration's STS

            // prefetch next node's edges (covers mix+epilogue latency)
            int nend = end;
            ed0 = make_int2(0, 0); ed1 = make_int2(0, 0);
            if (n + 1 < ne) {
                nend = g_rowptr[n + 2];
                if (end + lane < nend)      ed0 = eg[end + lane];
                if (end + 32 + lane < nend) ed1 = eg[end + 32 + lane];
            }

            // issue Gram-history loads; mix covers their latency
            float2 gjv[5];
#pragma unroll
            for (int j = 0; j < 5; j++)
                if (j < npairs && j != slot) gjv[j] = ((const float2*)g_G[j])[row];

            // channel mix: packed f32x2 FMA, Theta pairs from shared
            ull o0 = 0ull, o1 = 0ull;
#pragma unroll
            for (int m = 0; m < 32; ++m) {
                ull t0 = su->sThU[2 * m][lane];
                ull t1 = su->sThU[2 * m + 1][lane];
                fma2(o0, t0, splat2(__shfl_sync(0xffffffffu, acc.x, m)));
                fma2(o1, t1, splat2(__shfl_sync(0xffffffffu, acc.y, m)));
            }
            float2 m0 = unpack2(o0), m1 = unpack2(o1);
            float2 mix = make_float2(m0.x + m1.x, m0.y + m1.y);

            // epilogue
            float2 val = make_float2(bb.x + 0.5f * mix.x, bb.y + 0.5f * mix.y);
            ((float2*)g_F[slot])[row] = val;
            float2 gn = make_float2(val.x - uu.x, val.y - uu.y);
            ((float2*)g_G[slot])[row] = gn;
            if (wr_next) {
                ((float2*)g_u)[row] = val;
                ((float2*)wdst)[row] =
                    make_float2(2.f * fmaxf(val.x, 0.f) - val.x + bb.x,
                                2.f * fmaxf(val.y, 0.f) - val.y + bb.y);
            }
#pragma unroll
            for (int j = 0; j < 5; j++) {
                if (j < npairs) {
                    float2 gj = (j == slot) ? gn : gjv[j];
                    p[j] = fmaf(gn.x, gj.x, fmaf(gn.y, gj.y, p[j]));
                }
            }
            beg = end; end = nend;
        }
    }

#pragma unroll
    for (int j = 0; j < 5; ++j)
        for (int off = 16; off > 0; off >>= 1)
            p[j] += __shfl_down_sync(0xffffffffu, p[j], off);
    __syncthreads();
    if (lane == 0)
        for (int j = 0; j < 5; ++j) red[warp][j] = (double)p[j];
    __syncthreads();
    if (threadIdx.x < npairs) {
        int j = threadIdx.x;
        double s = 0.0;
        for (int ww = 0; ww < TPB / 32; ww++) s += red[ww][j];
        atomicAdd(&target[j], s);
    }
}

// ---------------- combine(k): Gram merge + 5x5 solve + u_new (+ fused decode at k=4) ----------------
__device__ void combine_phase(int k, float* sa, const float* __restrict__ decW,
                              float* __restrict__ out) {
    if (threadIdx.x == 0) {
        double M[5][5];
        const double* base = g_GGbuf[k & 1];
        int c = 0;
        for (int i = 0; i < 5; i++)
            for (int j = 0; j <= i; j++) { M[i][j] = base[c]; M[j][i] = base[c]; c++; }
        if (k > 0) {
            int idx = k - 1;
            const double* row = g_GGrow[(k - 1) & 1];
            for (int j = 0; j < 5; j++) { M[idx][j] = row[j]; M[j][idx] = row[j]; }
        }
        if (blockIdx.x == 0 && k < AAM - 1) {
            c = 0;
            for (int i = 0; i < 5; i++)
                for (int j = 0; j <= i; j++) g_GGbuf[(k + 1) & 1][c++] = M[i][j];
            for (int j = 0; j < 5; j++) g_GGrow[k & 1][j] = 0.0;
        }
        float A[5][6];
        for (int i = 0; i < 5; i++) {
            for (int j = 0; j < 5; j++) A[i][j] = (float)M[i][j];
            A[i][i] += 1e-4f;
            A[i][5] = 1.f;
        }
        for (int kk = 0; kk < 5; kk++) {
            int piv = kk; float mx = fabsf(A[kk][kk]);
            for (int r = kk + 1; r < 5; r++)
                if (fabsf(A[r][kk]) > mx) { mx = fabsf(A[r][kk]); piv = r; }
            if (piv != kk)
                for (int j = 0; j < 6; j++) { float t = A[kk][j]; A[kk][j] = A[piv][j]; A[piv][j] = t; }
            float inv = 1.f / A[kk][kk];
            for (int r = kk + 1; r < 5; r++) {
                float f = A[r][kk] * inv;
                for (int j = kk; j < 6; j++) A[r][j] -= f * A[kk][j];
            }
        }
        float a[5];
        for (int kk = 4; kk >= 0; kk--) {
            float s = A[kk][5];
            for (int j = kk + 1; j < 5; j++) s -= A[kk][j] * a[j];
            a[kk] = s / A[kk][kk];
        }
        float sum = a[0] + a[1] + a[2] + a[3] + a[4];
        for (int j = 0; j < 5; j++) sa[j] = a[j] / sum;
    }
    __syncthreads();
    float a0 = sa[0], a1 = sa[1], a2 = sa[2], a3 = sa[3], a4 = sa[4];

    int warp = threadIdx.x >> 5, lane = threadIdx.x & 31;
    int g = blockIdx.x * (TPB / 32) + warp;
    const float2* F0 = (const float2*)g_F[0];
    const float2* F1 = (const float2*)g_F[1];
    const float2* F2 = (const float2*)g_F[2];
    const float2* F3 = (const float2*)g_F[3];
    const float2* F4 = (const float2*)g_F[4];
    for (int node = g; node < N_NODES; node += NWARPS) {
        int idx = node * 32 + lane;
        float2 f0 = F0[idx], f1 = F1[idx], f2 = F2[idx], f3 = F3[idx], f4 = F4[idx];
        float2 un;
        un.x = a0 * f0.x + a1 * f1.x + a2 * f2.x + a3 * f3.x + a4 * f4.x;
        un.y = a0 * f0.y + a1 * f1.y + a2 * f2.y + a3 * f3.y + a4 * f4.y;
        if (k < AAM - 1) {
            ((float2*)g_u)[idx] = un;
            float2 bb = ((const float2*)g_b)[idx];
            ((float2*)g_wbuf[0])[idx] =
                make_float2(2.f * fmaxf(un.x, 0.f) - un.x + bb.x,
                            2.f * fmaxf(un.y, 0.f) - un.y + bb.y);
        } else {
            float rx = fmaxf(un.x, 0.f), ry = fmaxf(un.y, 0.f);
            int o = lane & 15, half = lane >> 4;
            float acc = 0.f;
#pragma unroll
            for (int i = 0; i < 16; i++) {
                int m = half * 16 + i;
                float sx = __shfl_sync(0xffffffffu, rx, m);
                float sy = __shfl_sync(0xffffffffu, ry, m);
                acc = fmaf(sx, decW[(2 * m) * 16 + o], acc);
                acc = fmaf(sy, decW[(2 * m + 1) * 16 + o], acc);
            }
            acc += __shfl_down_sync(0xffffffffu, acc, 16);
            if (half == 0) out[node * 16 + o] = acc;
        }
    }
}

// ---------------- the single persistent kernel ----------------
__global__ void __launch_bounds__(TPB, 2) k_mega(
    const float* __restrict__ x, const int* __restrict__ ei,
    const float* __restrict__ ew, const float* __restrict__ encW,
    const float* __restrict__ encb, const float* __restrict__ cayB,
    const float* __restrict__ decW, float* __restrict__ out)
{
    __shared__ SmemU su;
    __shared__ int2 sedge[TPB / 32][64];   // 8KB per-warp staging
    __shared__ double red[TPB / 32][5];
    __shared__ float sa[5];

    const int* src = ei;
    const int* dst = ei + N_EDGES;
    int gtid = blockIdx.x * TPB + threadIdx.x;

    // A: zero counters + Gram buf
    for (int i = gtid; i < N_NODES; i += NTHREADS) g_cur[i] = 0;
    if (gtid < 15) g_GGbuf[0][gtid] = 0.0;
    gbar();

    // B: degree histogram || encoder + u0/w0
    for (int e = gtid; e < N_EDGES; e += NTHREADS) atomicAdd(&g_cur[dst[e]], 1);
    encode_phase(x, encW, encb, sedge);
    gbar();

    // C: prefix scan (block 0) || Cayley theta (block 1)
    if (blockIdx.x == 0) {
        int t = threadIdx.x;
        const int CH = (N_NODES + TPB - 1) / TPB;   // 20
        int beg = t * CH, end = beg + CH; if (end > N_NODES) end = N_NODES;
        int s = 0;
        for (int i = beg; i < end; i++) s += g_cur[i];
        su.part[t] = s;
        __syncthreads();
        for (int d = 1; d < TPB; d <<= 1) {
            int v = (t >= d) ? su.part[t - d] : 0;
            __syncthreads();
            su.part[t] += v;
            __syncthreads();
        }
        int off = (t > 0) ? su.part[t - 1] : 0;
        for (int i = beg; i < end; i++) {
            int c = g_cur[i];
            g_rowptr[i] = off;
            g_cur[i]    = off;
            off += c;
        }
        if (t == 0) g_rowptr[N_NODES] = N_EDGES;
    } else if (blockIdx.x == 1) {
        theta_phase(cayB, &su);
    }
    gbar();

    // D: CSR scatter || balanced warp partition || stage Theta
    for (int e = gtid; e < N_EDGES; e += NTHREADS) {
        int d = dst[e];
        int p = atomicAdd(&g_cur[d], 1);
        g_edge[p] = make_int2(src[e], __float_as_int(ew[e]));
    }
    if (gtid <= NWARPS) {
        if (gtid == NWARPS) {
            g_wstart[NWARPS] = N_NODES;
        } else {
            long long target = (long long)gtid * COST_TOTAL / NWARPS;
            int lo = 0, hi = N_NODES;
            while (lo < hi) {
                int mid = (lo + hi) >> 1;
                long long c = (long long)g_rowptr[mid] + (long long)NODE_COST * mid;
                if (c < target) lo = mid + 1; else hi = mid;
            }
            g_wstart[gtid] = lo;
        }
    }
    for (int i = threadIdx.x; i < D_HID * 32; i += TPB)
        ((ull*)su.sThU)[i] = ((const ull*)g_ThT)[i];
    gbar();

    // history: 5 PR sweeps (w ping-pong), Gram lower-tri into GGbuf[0]
    for (int i = 0; i < AAM; i++) {
        spmm_phase(i, i + 1, &g_GGbuf[0][i * (i + 1) / 2], (i < AAM - 1) ? 1 : 0,
                   g_wbuf[i & 1], g_wbuf[(i + 1) & 1], &su, sedge, red);
        gbar();
    }

    // Anderson: combine -> spmm (last g() dead); final combine fuses decode
    for (int k = 0; k < AAM; k++) {
        combine_phase(k, sa, decW, out);
        if (k < AAM - 1) {
            gbar();
            spmm_phase(k, 5, g_GGrow[k & 1], 0, g_wbuf[0], 0, &su, sedge, red);
            gbar();
        }
    }
}

// ---------------- launch: ONE kernel ----------------
extern "C" void kernel_launch(void* const* d_in, const int* in_sizes, int n_in,
                              void* d_out, int out_size) {
    const float* x    = (const float*)d_in[0];
    const int*   ei   = (const int*)  d_in[1];
    const float* ew   = (const float*)d_in[2];
    const float* encW = (const float*)d_in[3];
    const float* encb = (const float*)d_in[4];
    const float* cayB = (const float*)d_in[5];
    const float* decW = (const float*)d_in[6];
    float* out = (float*)d_out;

    k_mega<<<GRID_BLOCKS, TPB>>>(x, ei, ew, encW, encb, cayB, decW, out);
}

// round 7
// speedup vs baseline: 1.0416x; 1.0416x over previous
#include <cuda_runtime.h>

#define N_NODES 10000
#define N_EDGES 320000
#define D_IN    128
#define D_HID   64
#define D_OUT   16
#define NH      (N_NODES * D_HID)
#define AAM     5
#define TPB         512
#define GRID_BLOCKS 296              // 148 SMs x 2 blocks guaranteed resident
#define NWARPS      (GRID_BLOCKS * (TPB / 32))   // 4736
#define NTHREADS    (GRID_BLOCKS * TPB)
#define NODE_COST   32
#define COST_TOTAL  (N_EDGES + NODE_COST * N_NODES)

typedef unsigned long long ull;

// ---------------- device scratch ----------------
__device__ float  g_b[NH];
__device__ float  g_u[NH];
__device__ float  g_wbuf[2][NH];          // ping-pong SPMM input
__device__ float  g_F[AAM][NH];
__device__ float  g_G[AAM][NH];
__device__ float  g_ThT[D_HID * D_HID];   // ThT[k*64+c] = Theta[c][k]
__device__ int    g_rowptr[N_NODES + 1];
__device__ int    g_cur[N_NODES];
__device__ int2   g_edge[N_EDGES];
__device__ int    g_wstart[NWARPS + 1];
__device__ double g_GGbuf[2][15];
__device__ double g_GGrow[2][5];
__device__ unsigned          g_bar_cnt;
__device__ volatile unsigned g_bar_gen;

union SmemU {
    struct { float M[64][128]; float fct[64]; } th;
    ull  sThU[D_HID][32];                 // packed Theta pairs for mix
    int  part[TPB];
};

// ---------------- f32x2 helpers ----------------
__device__ __forceinline__ void fma2(ull& d, ull a, ull b) {
    asm("fma.rn.f32x2 %0, %1, %2, %0;" : "+l"(d) : "l"(a), "l"(b));
}
__device__ __forceinline__ ull splat2(float s) {
    ull r; asm("mov.b64 %0, {%1, %1};" : "=l"(r) : "f"(s)); return r;
}
__device__ __forceinline__ float2 unpack2(ull v) {
    float2 r; asm("mov.b64 {%0, %1}, %2;" : "=f"(r.x), "=f"(r.y) : "l"(v)); return r;
}

// ---------------- software grid barrier ----------------
__device__ __forceinline__ void gbar() {
    __syncthreads();
    if (threadIdx.x == 0) {
        __threadfence();
        unsigned gen = g_bar_gen;
        if (atomicAdd(&g_bar_cnt, 1u) == GRID_BLOCKS - 1u) {
            g_bar_cnt = 0u;
            __threadfence();
            g_bar_gen = gen + 1u;
        } else {
            while (g_bar_gen == gen) { __nanosleep(64); }
        }
        __threadfence();
    }
    __syncthreads();
}

// ---------------- Cayley: Theta = (I+Om)^-1 (I-Om) ----------------
__device__ void theta_phase(const float* __restrict__ B, SmemU* su) {
    int tid = threadIdx.x;
    for (int idx = tid; idx < 64 * 64; idx += TPB) {
        int i = idx >> 6, j = idx & 63;
        float om = 0.5f * (B[i * 64 + j] - B[j * 64 + i]);
        float e  = (i == j) ? 1.f : 0.f;
        su->th.M[i][j]      = e + om;
        su->th.M[i][64 + j] = e - om;
    }
    __syncthreads();
    for (int k = 0; k < 64; k++) {
        float inv = 1.f / su->th.M[k][k];
        __syncthreads();
        for (int j = tid; j < 128; j += TPB) su->th.M[k][j] *= inv;
        __syncthreads();
        for (int r = tid; r < 64; r += TPB) su->th.fct[r] = su->th.M[r][k];
        __syncthreads();
        for (int idx = tid; idx < 64 * 128; idx += TPB) {
            int r = idx >> 7, j = idx & 127;
            if (r != k) su->th.M[r][j] -= su->th.fct[r] * su->th.M[k][j];
        }
        __syncthreads();
    }
    for (int idx = tid; idx < 64 * 64; idx += TPB) {
        int k = idx >> 6, c = idx & 63;
        g_ThT[idx] = su->th.M[c][64 + k];
    }
}

// ---------------- encoder + u0/w0 ----------------
__device__ void encode_phase(const float* __restrict__ x, const float* __restrict__ W,
                             const float* __restrict__ bias) {
    int warp = threadIdx.x >> 5, cp = threadIdx.x & 31;
    int g = blockIdx.x * (TPB / 32) + warp;
    const float2* __restrict__ W2 = (const float2*)W;
    float2 bsv = ((const float2*)bias)[cp];
    for (int node = g; node < N_NODES; node += NWARPS) {
        const float* __restrict__ xr = x + node * D_IN;
        float2 acc = bsv;
#pragma unroll 16
        for (int k = 0; k < D_IN; k++) {
            float  xk = xr[k];
            float2 w2 = W2[k * 32 + cp];
            acc.x = fmaf(xk, w2.x, acc.x);
            acc.y = fmaf(xk, w2.y, acc.y);
        }
        int row = node * 32 + cp;
        ((float2*)g_b)[row] = acc;
        ((float2*)g_u)[row] = acc;
        ((float2*)g_wbuf[0])[row] = make_float2(2.f * fmaxf(acc.x, 0.f),
                                                2.f * fmaxf(acc.y, 0.f));
    }
}

// ---------------- half-warp float4 gather: one LDG.128 fetches TWO edges' rows ----
// lanes 0-15 accumulate even edges, 16-31 odd edges; xor-combine; remap to
// float2-per-lane layout (lane m = channels 2m, 2m+1).
__device__ __forceinline__ float2 gather_f4(const int2* __restrict__ eg,
                                            const float4* __restrict__ wv4,
                                            int beg, int end, int lane) {
    const unsigned FULL = 0xffffffffu;
    int half = lane >> 4;
    int cl   = lane & 15;
    float a0 = 0.f, a1 = 0.f, a2 = 0.f, a3 = 0.f;
    float b0 = 0.f, b1 = 0.f, b2 = 0.f, b3 = 0.f;
    int cnt = end - beg;
    for (int base = 0; base < cnt; base += 32) {
        int2 ed = make_int2(0, 0);                 // OOB -> weight 0.0f
        if (base + lane < cnt) ed = eg[beg + base + lane];
        int nb = cnt - base; if (nb > 32) nb = 32;
        int np = (nb + 1) >> 1;
#pragma unroll 4
        for (int i = 0; i < np; i++) {
            int srcl = 2 * i + half;
            int   s = __shfl_sync(FULL, ed.x, srcl);
            float w = __int_as_float(__shfl_sync(FULL, ed.y, srcl));
            float4 v = wv4[s * 16 + cl];
            if (i & 1) {
                b0 = fmaf(w, v.x, b0); b1 = fmaf(w, v.y, b1);
                b2 = fmaf(w, v.z, b2); b3 = fmaf(w, v.w, b3);
            } else {
                a0 = fmaf(w, v.x, a0); a1 = fmaf(w, v.y, a1);
                a2 = fmaf(w, v.z, a2); a3 = fmaf(w, v.w, a3);
            }
        }
    }
    a0 += b0; a1 += b1; a2 += b2; a3 += b3;
    a0 += __shfl_xor_sync(FULL, a0, 16);
    a1 += __shfl_xor_sync(FULL, a1, 16);
    a2 += __shfl_xor_sync(FULL, a2, 16);
    a3 += __shfl_xor_sync(FULL, a3, 16);
    // lane m wants channels 2m,2m+1 = comps (0,1) or (2,3) of lane m>>1
    int srcl = lane >> 1;
    float lx = __shfl_sync(FULL, a0, srcl);
    float ly = __shfl_sync(FULL, a1, srcl);
    float hx = __shfl_sync(FULL, a2, srcl);
    float hy = __shfl_sync(FULL, a3, srcl);
    return (lane & 1) ? make_float2(hx, hy) : make_float2(lx, ly);
}

// ---------------- per-node epilogue: F, G, Gram partials, optional next u/w ----------------
__device__ __forceinline__ void epilogue(int node, int lane, float2 mix, int slot,
                                         int npairs, int wr_next, float* __restrict__ wdst,
                                         float* p) {
    int row = node * 32 + lane;
    float2 bb = ((const float2*)g_b)[row];
    float2 uu = ((const float2*)g_u)[row];
    float2 val = make_float2(bb.x + 0.5f * mix.x, bb.y + 0.5f * mix.y);
    ((float2*)g_F[slot])[row] = val;
    float2 gn = make_float2(val.x - uu.x, val.y - uu.y);
    ((float2*)g_G[slot])[row] = gn;
    if (wr_next) {
        ((float2*)g_u)[row] = val;
        ((float2*)wdst)[row] = make_float2(2.f * fmaxf(val.x, 0.f) - val.x + bb.x,
                                           2.f * fmaxf(val.y, 0.f) - val.y + bb.y);
    }
    for (int j = 0; j < npairs; ++j) {
        float2 gj = (j == slot) ? gn : ((const float2*)g_G[j])[row];
        p[j] = fmaf(gn.x, gj.x, fmaf(gn.y, gj.y, p[j]));
    }
}

// ---------------- fused SPMM + mix + G + Gram partials ----------------
__device__ void spmm_phase(int slot, int npairs, double* target, int wr_next,
                           const float* __restrict__ wsrc, float* __restrict__ wdst,
                           SmemU* su, double (*red)[5]) {
    int warp = threadIdx.x >> 5, lane = threadIdx.x & 31;
    int w = blockIdx.x * (TPB / 32) + warp;
    const int2*   __restrict__ eg  = g_edge;
    const float4* __restrict__ wv4 = (const float4*)wsrc;
    float p[5];
#pragma unroll
    for (int j = 0; j < 5; j++) p[j] = 0.f;

    int n = g_wstart[w], ne = g_wstart[w + 1];

    // pairs: shared Theta-row LDS, batched mix
    for (; n + 1 < ne; n += 2) {
        int r0 = g_rowptr[n], r1 = g_rowptr[n + 1], r2 = g_rowptr[n + 2];
        float2 accA = gather_f4(eg, wv4, r0, r1, lane);
        float2 accB = gather_f4(eg, wv4, r1, r2, lane);
        ull oA0 = 0ull, oA1 = 0ull, oB0 = 0ull, oB1 = 0ull;
#pragma unroll
        for (int m = 0; m < 32; ++m) {
            ull t0 = su->sThU[2 * m][lane];
            ull t1 = su->sThU[2 * m + 1][lane];
            fma2(oA0, t0, splat2(__shfl_sync(0xffffffffu, accA.x, m)));
            fma2(oA1, t1, splat2(__shfl_sync(0xffffffffu, accA.y, m)));
            fma2(oB0, t0, splat2(__shfl_sync(0xffffffffu, accB.x, m)));
            fma2(oB1, t1, splat2(__shfl_sync(0xffffffffu, accB.y, m)));
        }
        float2 mA0 = unpack2(oA0), mA1 = unpack2(oA1);
        float2 mB0 = unpack2(oB0), mB1 = unpack2(oB1);
        epilogue(n,     lane, make_float2(mA0.x + mA1.x, mA0.y + mA1.y),
                 slot, npairs, wr_next, wdst, p);
        epilogue(n + 1, lane, make_float2(mB0.x + mB1.x, mB0.y + mB1.y),
                 slot, npairs, wr_next, wdst, p);
    }
    // tail single node
    if (n < ne) {
        int r0 = g_rowptr[n], r1 = g_rowptr[n + 1];
        float2 acc = gather_f4(eg, wv4, r0, r1, lane);
        ull o0 = 0ull, o1 = 0ull;
#pragma unroll
        for (int m = 0; m < 32; ++m) {
            ull t0 = su->sThU[2 * m][lane];
            ull t1 = su->sThU[2 * m + 1][lane];
            fma2(o0, t0, splat2(__shfl_sync(0xffffffffu, acc.x, m)));
            fma2(o1, t1, splat2(__shfl_sync(0xffffffffu, acc.y, m)));
        }
        float2 m0 = unpack2(o0), m1 = unpack2(o1);
        epilogue(n, lane, make_float2(m0.x + m1.x, m0.y + m1.y),
                 slot, npairs, wr_next, wdst, p);
    }

#pragma unroll
    for (int j = 0; j < 5; ++j)
        for (int off = 16; off > 0; off >>= 1)
            p[j] += __shfl_down_sync(0xffffffffu, p[j], off);
    __syncthreads();
    if (lane == 0)
        for (int j = 0; j < 5; ++j) red[warp][j] = (double)p[j];
    __syncthreads();
    if (threadIdx.x < npairs) {
        int j = threadIdx.x;
        double s = 0.0;
        for (int ww = 0; ww < TPB / 32; ww++) s += red[ww][j];
        atomicAdd(&target[j], s);
    }
}

// ---------------- combine(k): Gram merge + 5x5 solve + u_new (+ fused decode at k=4) ----------------
__device__ void combine_phase(int k, float* sa, const float* __restrict__ decW,
                              float* __restrict__ out) {
    if (threadIdx.x == 0) {
        double M[5][5];
        const double* base = g_GGbuf[k & 1];
        int c = 0;
        for (int i = 0; i < 5; i++)
            for (int j = 0; j <= i; j++) { M[i][j] = base[c]; M[j][i] = base[c]; c++; }
        if (k > 0) {
            int idx = k - 1;
            const double* row = g_GGrow[(k - 1) & 1];
            for (int j = 0; j < 5; j++) { M[idx][j] = row[j]; M[j][idx] = row[j]; }
        }
        if (blockIdx.x == 0 && k < AAM - 1) {
            c = 0;
            for (int i = 0; i < 5; i++)
                for (int j = 0; j <= i; j++) g_GGbuf[(k + 1) & 1][c++] = M[i][j];
            for (int j = 0; j < 5; j++) g_GGrow[k & 1][j] = 0.0;
        }
        float A[5][6];
        for (int i = 0; i < 5; i++) {
            for (int j = 0; j < 5; j++) A[i][j] = (float)M[i][j];
            A[i][i] += 1e-4f;
            A[i][5] = 1.f;
        }
        for (int kk = 0; kk < 5; kk++) {
            int piv = kk; float mx = fabsf(A[kk][kk]);
            for (int r = kk + 1; r < 5; r++)
                if (fabsf(A[r][kk]) > mx) { mx = fabsf(A[r][kk]); piv = r; }
            if (piv != kk)
                for (int j = 0; j < 6; j++) { float t = A[kk][j]; A[kk][j] = A[piv][j]; A[piv][j] = t; }
            float inv = 1.f / A[kk][kk];
            for (int r = kk + 1; r < 5; r++) {
                float f = A[r][kk] * inv;
                for (int j = kk; j < 6; j++) A[r][j] -= f * A[kk][j];
            }
        }
        float a[5];
        for (int kk = 4; kk >= 0; kk--) {
            float s = A[kk][5];
            for (int j = kk + 1; j < 5; j++) s -= A[kk][j] * a[j];
            a[kk] = s / A[kk][kk];
        }
        float sum = a[0] + a[1] + a[2] + a[3] + a[4];
        for (int j = 0; j < 5; j++) sa[j] = a[j] / sum;
    }
    __syncthreads();
    float a0 = sa[0], a1 = sa[1], a2 = sa[2], a3 = sa[3], a4 = sa[4];

    int warp = threadIdx.x >> 5, lane = threadIdx.x & 31;
    int g = blockIdx.x * (TPB / 32) + warp;
    const float2* F0 = (const float2*)g_F[0];
    const float2* F1 = (const float2*)g_F[1];
    const float2* F2 = (const float2*)g_F[2];
    const float2* F3 = (const float2*)g_F[3];
    const float2* F4 = (const float2*)g_F[4];
    for (int node = g; node < N_NODES; node += NWARPS) {
        int idx = node * 32 + lane;
        float2 f0 = F0[idx], f1 = F1[idx], f2 = F2[idx], f3 = F3[idx], f4 = F4[idx];
        float2 un;
        un.x = a0 * f0.x + a1 * f1.x + a2 * f2.x + a3 * f3.x + a4 * f4.x;
        un.y = a0 * f0.y + a1 * f1.y + a2 * f2.y + a3 * f3.y + a4 * f4.y;
        if (k < AAM - 1) {
            ((float2*)g_u)[idx] = un;
            float2 bb = ((const float2*)g_b)[idx];
            ((float2*)g_wbuf[0])[idx] =
                make_float2(2.f * fmaxf(un.x, 0.f) - un.x + bb.x,
                            2.f * fmaxf(un.y, 0.f) - un.y + bb.y);
        } else {
            float rx = fmaxf(un.x, 0.f), ry = fmaxf(un.y, 0.f);
            int o = lane & 15, half = lane >> 4;
            float acc = 0.f;
#pragma unroll
            for (int i = 0; i < 16; i++) {
                int m = half * 16 + i;
                float sx = __shfl_sync(0xffffffffu, rx, m);
                float sy = __shfl_sync(0xffffffffu, ry, m);
                acc = fmaf(sx, decW[(2 * m) * 16 + o], acc);
                acc = fmaf(sy, decW[(2 * m + 1) * 16 + o], acc);
            }
            acc += __shfl_down_sync(0xffffffffu, acc, 16);
            if (half == 0) out[node * 16 + o] = acc;
        }
    }
}

// ---------------- the single persistent kernel ----------------
__global__ void __launch_bounds__(TPB, 2) k_mega(
    const float* __restrict__ x, const int* __restrict__ ei,
    const float* __restrict__ ew, const float* __restrict__ encW,
    const float* __restrict__ encb, const float* __restrict__ cayB,
    const float* __restrict__ decW, float* __restrict__ out)
{
    __shared__ SmemU su;
    __shared__ double red[TPB / 32][5];
    __shared__ float sa[5];

    const int* src = ei;
    const int* dst = ei + N_EDGES;
    int gtid = blockIdx.x * TPB + threadIdx.x;

    // A: zero counters + Gram buf
    for (int i = gtid; i < N_NODES; i += NTHREADS) g_cur[i] = 0;
    if (gtid < 15) g_GGbuf[0][gtid] = 0.0;
    gbar();

    // B: degree histogram || encoder + u0/w0
    for (int e = gtid; e < N_EDGES; e += NTHREADS) atomicAdd(&g_cur[dst[e]], 1);
    encode_phase(x, encW, encb);
    gbar();

    // C: prefix scan (block 0) || Cayley theta (block 1)
    if (blockIdx.x == 0) {
        int t = threadIdx.x;
        const int CH = (N_NODES + TPB - 1) / TPB;   // 20
        int beg = t * CH, end = beg + CH; if (end > N_NODES) end = N_NODES;
        int s = 0;
        for (int i = beg; i < end; i++) s += g_cur[i];
        su.part[t] = s;
        __syncthreads();
        for (int d = 1; d < TPB; d <<= 1) {
            int v = (t >= d) ? su.part[t - d] : 0;
            __syncthreads();
            su.part[t] += v;
            __syncthreads();
        }
        int off = (t > 0) ? su.part[t - 1] : 0;
        for (int i = beg; i < end; i++) {
            int c = g_cur[i];
            g_rowptr[i] = off;
            g_cur[i]    = off;
            off += c;
        }
        if (t == 0) g_rowptr[N_NODES] = N_EDGES;
    } else if (blockIdx.x == 1) {
        theta_phase(cayB, &su);
    }
    gbar();

    // D: CSR scatter || balanced warp partition || stage Theta
    for (int e = gtid; e < N_EDGES; e += NTHREADS) {
        int d = dst[e];
        int p = atomicAdd(&g_cur[d], 1);
        g_edge[p] = make_int2(src[e], __float_as_int(ew[e]));
    }
    if (gtid <= NWARPS) {
        if (gtid == NWARPS) {
            g_wstart[NWARPS] = N_NODES;
        } else {
            long long target = (long long)gtid * COST_TOTAL / NWARPS;
            int lo = 0, hi = N_NODES;
            while (lo < hi) {
                int mid = (lo + hi) >> 1;
                long long c = (long long)g_rowptr[mid] + (long long)NODE_COST * mid;
                if (c < target) lo = mid + 1; else hi = mid;
            }
            g_wstart[gtid] = lo;
        }
    }
    for (int i = threadIdx.x; i < D_HID * 32; i += TPB)
        ((ull*)su.sThU)[i] = ((const ull*)g_ThT)[i];
    gbar();

    // history: 5 PR sweeps (w ping-pong), Gram lower-tri into GGbuf[0]
    for (int i = 0; i < AAM; i++) {
        spmm_phase(i, i + 1, &g_GGbuf[0][i * (i + 1) / 2], (i < AAM - 1) ? 1 : 0,
                   g_wbuf[i & 1], g_wbuf[(i + 1) & 1], &su, red);
        gbar();
    }

    // Anderson: combine -> spmm (last g() dead); final combine fuses decode
    for (int k = 0; k < AAM; k++) {
        combine_phase(k, sa, decW, out);
        if (k < AAM - 1) {
            gbar();
            spmm_phase(k, 5, g_GGrow[k & 1], 0, g_wbuf[0], 0, &su, red);
            gbar();
        }
    }
}

// ---------------- launch: ONE kernel ----------------
extern "C" void kernel_launch(void* const* d_in, const int* in_sizes, int n_in,
                              void* d_out, int out_size) {
    const float* x    = (const float*)d_in[0];
    const int*   ei   = (const int*)  d_in[1];
    const float* ew   = (const float*)d_in[2];
    const float* encW = (const float*)d_in[3];
    const float* encb = (const float*)d_in[4];
    const float* cayB = (const float*)d_in[5];
    const float* decW = (const float*)d_in[6];
    float* out = (float*)d_out;

    k_mega<<<GRID_BLOCKS, TPB>>>(x, ei, ew, encW, encb, cayB, decW, out);
}

// round 8
// speedup vs baseline: 1.1094x; 1.0651x over previous
#include <cuda_runtime.h>

#define N_NODES 10000
#define N_EDGES 320000
#define D_IN    128
#define D_HID   64
#define D_OUT   16
#define NH      (N_NODES * D_HID)
#define AAM     5
#define TPB         512
#define GRID_BLOCKS 296              // 148 SMs x 2 blocks guaranteed resident
#define NWARPS      (GRID_BLOCKS * (TPB / 32))   // 4736
#define NTHREADS    (GRID_BLOCKS * TPB)
#define NODE_COST   48
#define COST_TOTAL  (N_EDGES + NODE_COST * N_NODES)

typedef unsigned long long ull;

// ---------------- device scratch ----------------
__device__ float  g_b[NH];
__device__ float  g_u[NH];
__device__ float  g_wbuf[2][NH];          // ping-pong SPMM input
__device__ float  g_F[AAM][NH];
__device__ float  g_G[AAM][NH];
__device__ float  g_ThT[D_HID * D_HID];   // ThT[k*64+c] = Theta[c][k]
__device__ int    g_rowptr[N_NODES + 1];
__device__ int    g_cur[N_NODES];
__device__ int2   g_edge[N_EDGES];
__device__ int    g_wstart[NWARPS + 1];
__device__ double g_GGbuf[2][15];
__device__ double g_GGrow[2][5];
__device__ unsigned          g_bar_cnt;
__device__ volatile unsigned g_bar_gen;

union SmemU {
    struct { float M[64][128]; float fct[64]; } th;            // 33 KB (setup)
    struct {
        ull A[32][32];            // ThA[m][l] = (Th[2l][2m],   Th[2l][2m+1])
        ull B[32][32];            // ThB[m][l] = (Th[2l+1][2m], Th[2l+1][2m+1])
        ull s[TPB / 32][2][32];   // per-warp staged s vectors (A, B)
    } mix;                        // 24 KB (spmm phases)
    int part[TPB];
};

// ---------------- f32x2 helpers ----------------
__device__ __forceinline__ void fma2(ull& d, ull a, ull b) {
    asm("fma.rn.f32x2 %0, %1, %2, %0;" : "+l"(d) : "l"(a), "l"(b));
}
__device__ __forceinline__ ull pack2(float2 v) {
    ull r; asm("mov.b64 %0, {%1, %2};" : "=l"(r) : "f"(v.x), "f"(v.y)); return r;
}
__device__ __forceinline__ float2 unpack2(ull v) {
    float2 r; asm("mov.b64 {%0, %1}, %2;" : "=f"(r.x), "=f"(r.y) : "l"(v)); return r;
}

// ---------------- software grid barrier ----------------
__device__ __forceinline__ void gbar() {
    __syncthreads();
    if (threadIdx.x == 0) {
        __threadfence();
        unsigned gen = g_bar_gen;
        if (atomicAdd(&g_bar_cnt, 1u) == GRID_BLOCKS - 1u) {
            g_bar_cnt = 0u;
            __threadfence();
            g_bar_gen = gen + 1u;
        } else {
            while (g_bar_gen == gen) { __nanosleep(64); }
        }
        __threadfence();
    }
    __syncthreads();
}

// ---------------- Cayley: Theta = (I+Om)^-1 (I-Om) ----------------
__device__ void theta_phase(const float* __restrict__ B, SmemU* su) {
    int tid = threadIdx.x;
    for (int idx = tid; idx < 64 * 64; idx += TPB) {
        int i = idx >> 6, j = idx & 63;
        float om = 0.5f * (B[i * 64 + j] - B[j * 64 + i]);
        float e  = (i == j) ? 1.f : 0.f;
        su->th.M[i][j]      = e + om;
        su->th.M[i][64 + j] = e - om;
    }
    __syncthreads();
    for (int k = 0; k < 64; k++) {
        float inv = 1.f / su->th.M[k][k];
        __syncthreads();
        for (int j = tid; j < 128; j += TPB) su->th.M[k][j] *= inv;
        __syncthreads();
        for (int r = tid; r < 64; r += TPB) su->th.fct[r] = su->th.M[r][k];
        __syncthreads();
        for (int idx = tid; idx < 64 * 128; idx += TPB) {
            int r = idx >> 7, j = idx & 127;
            if (r != k) su->th.M[r][j] -= su->th.fct[r] * su->th.M[k][j];
        }
        __syncthreads();
    }
    for (int idx = tid; idx < 64 * 64; idx += TPB) {
        int k = idx >> 6, c = idx & 63;
        g_ThT[idx] = su->th.M[c][64 + k];
    }
}

// ---------------- encoder + u0/w0 ----------------
__device__ void encode_phase(const float* __restrict__ x, const float* __restrict__ W,
                             const float* __restrict__ bias) {
    int warp = threadIdx.x >> 5, cp = threadIdx.x & 31;
    int g = blockIdx.x * (TPB / 32) + warp;
    const float2* __restrict__ W2 = (const float2*)W;
    float2 bsv = ((const float2*)bias)[cp];
    for (int node = g; node < N_NODES; node += NWARPS) {
        const float* __restrict__ xr = x + node * D_IN;
        float2 acc = bsv;
#pragma unroll 16
        for (int k = 0; k < D_IN; k++) {
            float  xk = xr[k];
            float2 w2 = W2[k * 32 + cp];
            acc.x = fmaf(xk, w2.x, acc.x);
            acc.y = fmaf(xk, w2.y, acc.y);
        }
        int row = node * 32 + cp;
        ((float2*)g_b)[row] = acc;
        ((float2*)g_u)[row] = acc;
        ((float2*)g_wbuf[0])[row] = make_float2(2.f * fmaxf(acc.x, 0.f),
                                                2.f * fmaxf(acc.y, 0.f));
    }
}

// ---------------- interleaved dual-node gather ----------------
__device__ __forceinline__ void gather2(const int2* __restrict__ eg,
                                        const float2* __restrict__ wv,
                                        int eA, int endA, int eB, int endB,
                                        int lane, float2& outA, float2& outB) {
    float2 aA0 = {0.f, 0.f}, aA1 = {0.f, 0.f};
    float2 aB0 = {0.f, 0.f}, aB1 = {0.f, 0.f};
    while (eA + 4 <= endA && eB + 4 <= endB) {
        int2 dA0 = eg[eA], dA1 = eg[eA + 1], dA2 = eg[eA + 2], dA3 = eg[eA + 3];
        int2 dB0 = eg[eB], dB1 = eg[eB + 1], dB2 = eg[eB + 2], dB3 = eg[eB + 3];
        float2 vA0 = wv[dA0.x * 32 + lane], vA1 = wv[dA1.x * 32 + lane];
        float2 vA2 = wv[dA2.x * 32 + lane], vA3 = wv[dA3.x * 32 + lane];
        float2 vB0 = wv[dB0.x * 32 + lane], vB1 = wv[dB1.x * 32 + lane];
        float2 vB2 = wv[dB2.x * 32 + lane], vB3 = wv[dB3.x * 32 + lane];
        float wA0 = __int_as_float(dA0.y), wA1 = __int_as_float(dA1.y);
        float wA2 = __int_as_float(dA2.y), wA3 = __int_as_float(dA3.y);
        float wB0 = __int_as_float(dB0.y), wB1 = __int_as_float(dB1.y);
        float wB2 = __int_as_float(dB2.y), wB3 = __int_as_float(dB3.y);
        aA0.x = fmaf(wA0, vA0.x, aA0.x); aA0.y = fmaf(wA0, vA0.y, aA0.y);
        aA1.x = fmaf(wA1, vA1.x, aA1.x); aA1.y = fmaf(wA1, vA1.y, aA1.y);
        aA0.x = fmaf(wA2, vA2.x, aA0.x); aA0.y = fmaf(wA2, vA2.y, aA0.y);
        aA1.x = fmaf(wA3, vA3.x, aA1.x); aA1.y = fmaf(wA3, vA3.y, aA1.y);
        aB0.x = fmaf(wB0, vB0.x, aB0.x); aB0.y = fmaf(wB0, vB0.y, aB0.y);
        aB1.x = fmaf(wB1, vB1.x, aB1.x); aB1.y = fmaf(wB1, vB1.y, aB1.y);
        aB0.x = fmaf(wB2, vB2.x, aB0.x); aB0.y = fmaf(wB2, vB2.y, aB0.y);
        aB1.x = fmaf(wB3, vB3.x, aB1.x); aB1.y = fmaf(wB3, vB3.y, aB1.y);
        eA += 4; eB += 4;
    }
    for (; eA + 4 <= endA; eA += 4) {
        int2 d0 = eg[eA], d1 = eg[eA + 1], d2 = eg[eA + 2], d3 = eg[eA + 3];
        float2 v0 = wv[d0.x * 32 + lane], v1 = wv[d1.x * 32 + lane];
        float2 v2 = wv[d2.x * 32 + lane], v3 = wv[d3.x * 32 + lane];
        float w0 = __int_as_float(d0.y), w1 = __int_as_float(d1.y);
        float w2 = __int_as_float(d2.y), w3 = __int_as_float(d3.y);
        aA0.x = fmaf(w0, v0.x, aA0.x); aA0.y = fmaf(w0, v0.y, aA0.y);
        aA1.x = fmaf(w1, v1.x, aA1.x); aA1.y = fmaf(w1, v1.y, aA1.y);
        aA0.x = fmaf(w2, v2.x, aA0.x); aA0.y = fmaf(w2, v2.y, aA0.y);
        aA1.x = fmaf(w3, v3.x, aA1.x); aA1.y = fmaf(w3, v3.y, aA1.y);
    }
    for (; eA < endA; ++eA) {
        int2 d = eg[eA];
        float2 v = wv[d.x * 32 + lane];
        float ww = __int_as_float(d.y);
        aA0.x = fmaf(ww, v.x, aA0.x); aA0.y = fmaf(ww, v.y, aA0.y);
    }
    for (; eB + 4 <= endB; eB += 4) {
        int2 d0 = eg[eB], d1 = eg[eB + 1], d2 = eg[eB + 2], d3 = eg[eB + 3];
        float2 v0 = wv[d0.x * 32 + lane], v1 = wv[d1.x * 32 + lane];
        float2 v2 = wv[d2.x * 32 + lane], v3 = wv[d3.x * 32 + lane];
        float w0 = __int_as_float(d0.y), w1 = __int_as_float(d1.y);
        float w2 = __int_as_float(d2.y), w3 = __int_as_float(d3.y);
        aB0.x = fmaf(w0, v0.x, aB0.x); aB0.y = fmaf(w0, v0.y, aB0.y);
        aB1.x = fmaf(w1, v1.x, aB1.x); aB1.y = fmaf(w1, v1.y, aB1.y);
        aB0.x = fmaf(w2, v2.x, aB0.x); aB0.y = fmaf(w2, v2.y, aB0.y);
        aB1.x = fmaf(w3, v3.x, aB1.x); aB1.y = fmaf(w3, v3.y, aB1.y);
    }
    for (; eB < endB; ++eB) {
        int2 d = eg[eB];
        float2 v = wv[d.x * 32 + lane];
        float ww = __int_as_float(d.y);
        aB0.x = fmaf(ww, v.x, aB0.x); aB0.y = fmaf(ww, v.y, aB0.y);
    }
    outA = make_float2(aA0.x + aA1.x, aA0.y + aA1.y);
    outB = make_float2(aB0.x + aB1.x, aB0.y + aB1.y);
}

// ---------------- per-node epilogue ----------------
__device__ __forceinline__ void epilogue(int node, int lane, float2 mix, int slot,
                                         int npairs, int wr_next, float* __restrict__ wdst,
                                         float* p) {
    int row = node * 32 + lane;
    float2 bb = ((const float2*)g_b)[row];
    float2 uu = ((const float2*)g_u)[row];
    float2 val = make_float2(bb.x + 0.5f * mix.x, bb.y + 0.5f * mix.y);
    ((float2*)g_F[slot])[row] = val;
    float2 gn = make_float2(val.x - uu.x, val.y - uu.y);
    ((float2*)g_G[slot])[row] = gn;
    if (wr_next) {
        ((float2*)g_u)[row] = val;
        ((float2*)wdst)[row] = make_float2(2.f * fmaxf(val.x, 0.f) - val.x + bb.x,
                                           2.f * fmaxf(val.y, 0.f) - val.y + bb.y);
    }
    for (int j = 0; j < npairs; ++j) {
        float2 gj = (j == slot) ? gn : ((const float2*)g_G[j])[row];
        p[j] = fmaf(gn.x, gj.x, fmaf(gn.y, gj.y, p[j]));
    }
}

// ---------------- fused SPMM + shuffle-free mix + G + Gram partials ----------------
__device__ void spmm_phase(int slot, int npairs, double* target, int wr_next,
                           const float* __restrict__ wsrc, float* __restrict__ wdst,
                           SmemU* su, double (*red)[5]) {
    int warp = threadIdx.x >> 5, lane = threadIdx.x & 31;
    int w = blockIdx.x * (TPB / 32) + warp;
    const int2*   __restrict__ eg = g_edge;
    const float2* __restrict__ wv = (const float2*)wsrc;
    float p[5];
#pragma unroll
    for (int j = 0; j < 5; j++) p[j] = 0.f;

    int n = g_wstart[w], ne = g_wstart[w + 1];

    for (; n + 1 < ne; n += 2) {
        int r0 = g_rowptr[n], r1 = g_rowptr[n + 1], r2 = g_rowptr[n + 2];
        float2 accA, accB;
        gather2(eg, wv, r0, r1, r1, r2, lane, accA, accB);

        __syncwarp();
        su->mix.s[warp][0][lane] = pack2(accA);
        su->mix.s[warp][1][lane] = pack2(accB);
        __syncwarp();

        ull PA = 0ull, QA = 0ull, PB = 0ull, QB = 0ull;
#pragma unroll
        for (int m = 0; m < 32; ++m) {
            ull spA = su->mix.s[warp][0][m];   // broadcast LDS.64
            ull spB = su->mix.s[warp][1][m];
            ull TA  = su->mix.A[m][lane];
            ull TB  = su->mix.B[m][lane];
            fma2(PA, TA, spA); fma2(QA, TB, spA);
            fma2(PB, TA, spB); fma2(QB, TB, spB);
        }
        float2 pA = unpack2(PA), qA = unpack2(QA);
        float2 pB = unpack2(PB), qB = unpack2(QB);
        epilogue(n,     lane, make_float2(pA.x + pA.y, qA.x + qA.y),
                 slot, npairs, wr_next, wdst, p);
        epilogue(n + 1, lane, make_float2(pB.x + pB.y, qB.x + qB.y),
                 slot, npairs, wr_next, wdst, p);
    }
    if (n < ne) {
        int r0 = g_rowptr[n], r1 = g_rowptr[n + 1];
        float2 acc, dummy;
        gather2(eg, wv, r0, r1, r1, r1, lane, acc, dummy);
        __syncwarp();
        su->mix.s[warp][0][lane] = pack2(acc);
        __syncwarp();
        ull PA = 0ull, QA = 0ull;
#pragma unroll
        for (int m = 0; m < 32; ++m) {
            ull spA = su->mix.s[warp][0][m];
            fma2(PA, su->mix.A[m][lane], spA);
            fma2(QA, su->mix.B[m][lane], spA);
        }
        float2 pA = unpack2(PA), qA = unpack2(QA);
        epilogue(n, lane, make_float2(pA.x + pA.y, qA.x + qA.y),
                 slot, npairs, wr_next, wdst, p);
    }

#pragma unroll
    for (int j = 0; j < 5; ++j)
        for (int off = 16; off > 0; off >>= 1)
            p[j] += __shfl_down_sync(0xffffffffu, p[j], off);
    __syncthreads();
    if (lane == 0)
        for (int j = 0; j < 5; ++j) red[warp][j] = (double)p[j];
    __syncthreads();
    if (threadIdx.x < npairs) {
        int j = threadIdx.x;
        double s = 0.0;
        for (int ww = 0; ww < TPB / 32; ww++) s += red[ww][j];
        atomicAdd(&target[j], s);
    }
}

// ---------------- combine(k): Gram merge + 5x5 solve + u_new (+ fused decode at k=4) ----------------
__device__ void combine_phase(int k, float* sa, const float* __restrict__ decW,
                              float* __restrict__ out) {
    if (threadIdx.x == 0) {
        double M[5][5];
        const double* base = g_GGbuf[k & 1];
        int c = 0;
        for (int i = 0; i < 5; i++)
            for (int j = 0; j <= i; j++) { M[i][j] = base[c]; M[j][i] = base[c]; c++; }
        if (k > 0) {
            int idx = k - 1;
            const double* row = g_GGrow[(k - 1) & 1];
            for (int j = 0; j < 5; j++) { M[idx][j] = row[j]; M[j][idx] = row[j]; }
        }
        if (blockIdx.x == 0 && k < AAM - 1) {
            c = 0;
            for (int i = 0; i < 5; i++)
                for (int j = 0; j <= i; j++) g_GGbuf[(k + 1) & 1][c++] = M[i][j];
            for (int j = 0; j < 5; j++) g_GGrow[k & 1][j] = 0.0;
        }
        float A[5][6];
        for (int i = 0; i < 5; i++) {
            for (int j = 0; j < 5; j++) A[i][j] = (float)M[i][j];
            A[i][i] += 1e-4f;
            A[i][5] = 1.f;
        }
        for (int kk = 0; kk < 5; kk++) {
            int piv = kk; float mx = fabsf(A[kk][kk]);
            for (int r = kk + 1; r < 5; r++)
                if (fabsf(A[r][kk]) > mx) { mx = fabsf(A[r][kk]); piv = r; }
            if (piv != kk)
                for (int j = 0; j < 6; j++) { float t = A[kk][j]; A[kk][j] = A[piv][j]; A[piv][j] = t; }
            float inv = 1.f / A[kk][kk];
            for (int r = kk + 1; r < 5; r++) {
                float f = A[r][kk] * inv;
                for (int j = kk; j < 6; j++) A[r][j] -= f * A[kk][j];
            }
        }
        float a[5];
        for (int kk = 4; kk >= 0; kk--) {
            float s = A[kk][5];
            for (int j = kk + 1; j < 5; j++) s -= A[kk][j] * a[j];
            a[kk] = s / A[kk][kk];
        }
        float sum = a[0] + a[1] + a[2] + a[3] + a[4];
        for (int j = 0; j < 5; j++) sa[j] = a[j] / sum;
    }
    __syncthreads();
    float a0 = sa[0], a1 = sa[1], a2 = sa[2], a3 = sa[3], a4 = sa[4];

    int warp = threadIdx.x >> 5, lane = threadIdx.x & 31;
    int g = blockIdx.x * (TPB / 32) + warp;
    const float2* F0 = (const float2*)g_F[0];
    const float2* F1 = (const float2*)g_F[1];
    const float2* F2 = (const float2*)g_F[2];
    const float2* F3 = (const float2*)g_F[3];
    const float2* F4 = (const float2*)g_F[4];
    for (int node = g; node < N_NODES; node += NWARPS) {
        int idx = node * 32 + lane;
        float2 f0 = F0[idx], f1 = F1[idx], f2 = F2[idx], f3 = F3[idx], f4 = F4[idx];
        float2 un;
        un.x = a0 * f0.x + a1 * f1.x + a2 * f2.x + a3 * f3.x + a4 * f4.x;
        un.y = a0 * f0.y + a1 * f1.y + a2 * f2.y + a3 * f3.y + a4 * f4.y;
        if (k < AAM - 1) {
            ((float2*)g_u)[idx] = un;
            float2 bb = ((const float2*)g_b)[idx];
            ((float2*)g_wbuf[0])[idx] =
                make_float2(2.f * fmaxf(un.x, 0.f) - un.x + bb.x,
                            2.f * fmaxf(un.y, 0.f) - un.y + bb.y);
        } else {
            float rx = fmaxf(un.x, 0.f), ry = fmaxf(un.y, 0.f);
            int o = lane & 15, half = lane >> 4;
            float acc = 0.f;
#pragma unroll
            for (int i = 0; i < 16; i++) {
                int m = half * 16 + i;
                float sx = __shfl_sync(0xffffffffu, rx, m);
                float sy = __shfl_sync(0xffffffffu, ry, m);
                acc = fmaf(sx, decW[(2 * m) * 16 + o], acc);
                acc = fmaf(sy, decW[(2 * m + 1) * 16 + o], acc);
            }
            acc += __shfl_down_sync(0xffffffffu, acc, 16);
            if (half == 0) out[node * 16 + o] = acc;
        }
    }
}

// ---------------- the single persistent kernel ----------------
__global__ void __launch_bounds__(TPB, 2) k_mega(
    const float* __restrict__ x, const int* __restrict__ ei,
    const float* __restrict__ ew, const float* __restrict__ encW,
    const float* __restrict__ encb, const float* __restrict__ cayB,
    const float* __restrict__ decW, float* __restrict__ out)
{
    __shared__ SmemU su;
    __shared__ double red[TPB / 32][5];
    __shared__ float sa[5];

    const int* src = ei;
    const int* dst = ei + N_EDGES;
    int gtid = blockIdx.x * TPB + threadIdx.x;

    // A: zero counters + Gram buf
    for (int i = gtid; i < N_NODES; i += NTHREADS) g_cur[i] = 0;
    if (gtid < 15) g_GGbuf[0][gtid] = 0.0;
    gbar();

    // B: degree histogram || encoder + u0/w0
    for (int e = gtid; e < N_EDGES; e += NTHREADS) atomicAdd(&g_cur[dst[e]], 1);
    encode_phase(x, encW, encb);
    gbar();

    // C: prefix scan (block 0) || Cayley theta (block 1)
    if (blockIdx.x == 0) {
        int t = threadIdx.x;
        const int CH = (N_NODES + TPB - 1) / TPB;   // 20
        int beg = t * CH, end = beg + CH; if (end > N_NODES) end = N_NODES;
        int s = 0;
        for (int i = beg; i < end; i++) s += g_cur[i];
        su.part[t] = s;
        __syncthreads();
        for (int d = 1; d < TPB; d <<= 1) {
            int v = (t >= d) ? su.part[t - d] : 0;
            __syncthreads();
            su.part[t] += v;
            __syncthreads();
        }
        int off = (t > 0) ? su.part[t - 1] : 0;
        for (int i = beg; i < end; i++) {
            int c = g_cur[i];
            g_rowptr[i] = off;
            g_cur[i]    = off;
            off += c;
        }
        if (t == 0) g_rowptr[N_NODES] = N_EDGES;
    } else if (blockIdx.x == 1) {
        theta_phase(cayB, &su);
    }
    gbar();

    // D: CSR scatter || balanced warp partition || stage dual Theta layouts
    for (int e = gtid; e < N_EDGES; e += NTHREADS) {
        int d = dst[e];
        int p = atomicAdd(&g_cur[d], 1);
        g_edge[p] = make_int2(src[e], __float_as_int(ew[e]));
    }
    if (gtid <= NWARPS) {
        if (gtid == NWARPS) {
            g_wstart[NWARPS] = N_NODES;
        } else {
            long long target = (long long)gtid * COST_TOTAL / NWARPS;
            int lo = 0, hi = N_NODES;
            while (lo < hi) {
                int mid = (lo + hi) >> 1;
                long long c = (long long)g_rowptr[mid] + (long long)NODE_COST * mid;
                if (c < target) lo = mid + 1; else hi = mid;
            }
            g_wstart[gtid] = lo;
        }
    }
    for (int i = threadIdx.x; i < 1024; i += TPB) {
        int m = i >> 5, l = i & 31;
        float a0 = g_ThT[(2 * m) * 64 + 2 * l];
        float a1 = g_ThT[(2 * m + 1) * 64 + 2 * l];
        float b0 = g_ThT[(2 * m) * 64 + 2 * l + 1];
        float b1 = g_ThT[(2 * m + 1) * 64 + 2 * l + 1];
        su.mix.A[m][l] = pack2(make_float2(a0, a1));
        su.mix.B[m][l] = pack2(make_float2(b0, b1));
    }
    gbar();

    // history: 5 PR sweeps (w ping-pong), Gram lower-tri into GGbuf[0]
    for (int i = 0; i < AAM; i++) {
        spmm_phase(i, i + 1, &g_GGbuf[0][i * (i + 1) / 2], (i < AAM - 1) ? 1 : 0,
                   g_wbuf[i & 1], g_wbuf[(i + 1) & 1], &su, red);
        gbar();
    }

    // Anderson: combine -> spmm (last g() dead); final combine fuses decode
    for (int k = 0; k < AAM; k++) {
        combine_phase(k, sa, decW, out);
        if (k < AAM - 1) {
            gbar();
            spmm_phase(k, 5, g_GGrow[k & 1], 0, g_wbuf[0], 0, &su, red);
            gbar();
        }
    }
}

// ---------------- launch: ONE kernel ----------------
extern "C" void kernel_launch(void* const* d_in, const int* in_sizes, int n_in,
                              void* d_out, int out_size) {
    const float* x    = (const float*)d_in[0];
    const int*   ei   = (const int*)  d_in[1];
    const float* ew   = (const float*)d_in[2];
    const float* encW = (const float*)d_in[3];
    const float* encb = (const float*)d_in[4];
    const float* cayB = (const float*)d_in[5];
    const float* decW = (const float*)d_in[6];
    float* out = (float*)d_out;

    k_mega<<<GRID_BLOCKS, TPB>>>(x, ei, ew, encW, encb, cayB, decW, out);
}